// round 3
// baseline (speedup 1.0000x reference)
#include <cuda_runtime.h>

#define NB 128   // persistent CTAs (1/SM, all resident -> spin barrier safe)
#define NT 256   // 8 warps
#define TT 2048
#define BB 8
#define HD 512
#define DI 256

// ---------------- device scratch (no cudaMalloc allowed) ----------------
__device__ float g_hA[2 * BB * HD];      // double-buffered h1 broadcast
__device__ float g_hB[2 * BB * HD];      // double-buffered h2 broadcast
__device__ unsigned g_flags[NB];         // periods completed per CTA (4 L2 lines)

__global__ void init_kernel() {
    int i = blockIdx.x * blockDim.x + threadIdx.x;
    int stride = gridDim.x * blockDim.x;
    if (i < NB) g_flags[i] = 0u;
    for (int k = i; k < BB * HD; k += stride) g_hA[k] = 0.0f;          // h1(-1)
    for (int k = i; k < 2 * BB * HD; k += stride) g_hB[k] = 0.0f;      // h2(-1), h2(-2)
}

__device__ __forceinline__ float sigm(float x) {
    return __fdividef(1.0f, 1.0f + __expf(-x));
}
__device__ __forceinline__ float tanh_fast(float x) {
    return 2.0f * sigm(2.0f * x) - 1.0f;   // saturation-safe (expf overflow -> 0)
}

// Packed dual-FMA on the sm_103a f32x2 pipe.
__device__ __forceinline__ void ffma2(unsigned long long& d, unsigned long long a,
                                      unsigned long long b) {
    asm("fma.rn.f32x2 %0, %1, %2, %0;" : "+l"(d) : "l"(a), "l"(b));
}

// Wait until every CTA has completed >= target periods. 4 acquire loads per
// lane over 128 contiguous flags (4 L2 lines, no atomics, no CCTL flush).
__device__ __forceinline__ void poll_flags(int lane, unsigned target) {
    const unsigned* f = g_flags + lane;
    bool ok;
    do {
        unsigned a, b, c, d;
        asm volatile("ld.acquire.gpu.global.b32 %0, [%1];" : "=r"(a) : "l"(f)      : "memory");
        asm volatile("ld.acquire.gpu.global.b32 %0, [%1];" : "=r"(b) : "l"(f + 32) : "memory");
        asm volatile("ld.acquire.gpu.global.b32 %0, [%1];" : "=r"(c) : "l"(f + 64) : "memory");
        asm volatile("ld.acquire.gpu.global.b32 %0, [%1];" : "=r"(d) : "l"(f + 96) : "memory");
        ok = (a >= target) && (b >= target) && (c >= target) && (d >= target);
    } while (!__all_sync(0xffffffffu, ok));
}

// Gate dot: acc[r*8+b] (f32x2 k-pair partials) += rows [g4, g4+4) of mat x src[b].
template <int KP>
__device__ __forceinline__ void dot2(unsigned long long* acc, const float* __restrict__ mat,
                                     const float* __restrict__ src, int g4, int lane) {
#pragma unroll
    for (int it = 0; it < KP / 128; it++) {
        const int kb = it * 128 + lane * 4;
        ulonglong2 m[4];
#pragma unroll
        for (int r = 0; r < 4; r++)
            m[r] = *(const ulonglong2*)(mat + (g4 + r) * KP + kb);
#pragma unroll
        for (int b = 0; b < 8; b++) {
            ulonglong2 v = *(const ulonglong2*)(src + b * KP + kb);
#pragma unroll
            for (int r = 0; r < 4; r++) {
                ffma2(acc[r * 8 + b], m[r].x, v.x);
                ffma2(acc[r * 8 + b], m[r].y, v.y);
            }
        }
    }
}

// Fused 2-layer wavefront. Warp = (layer, column): warps 0-3 own layer-0
// columns j0..j0+3 (all 4 gates), warps 4-7 the same columns of layer 1.
// Cell state is a register of lanes 0-7; the whole gate->cell path is
// warp-local (shuffle reduce + 4-shfl gather, no smem round trip).
__global__ void __launch_bounds__(NT, 1) lstm_fused_kernel(
    const float* __restrict__ x,
    const float* __restrict__ u0W, const float* __restrict__ w0W,
    const float* __restrict__ u0b, const float* __restrict__ w0b,
    const float* __restrict__ u1W, const float* __restrict__ w1W,
    const float* __restrict__ u1b, const float* __restrict__ w1b,
    float* __restrict__ h2seq, float* __restrict__ hh, float* __restrict__ cc)
{
    extern __shared__ float sm[];
    float* sU0 = sm;                  // 16*512  rows (jl*4+g)
    float* sW0 = sU0 + 16 * HD;       // 16*256
    float* sU1 = sW0 + 16 * DI;       // 16*512
    float* sW1 = sU1 + 16 * HD;       // 16*512
    float* sA  = sW1 + 16 * HD;       // 8*512  h1(p-1) stage
    float* sB  = sA + BB * HD;        // 8*512  h2(p-2) stage
    float* sX  = sB + BB * HD;        // 8*256  x(p) stage

    const int tid  = threadIdx.x;
    const int bid  = blockIdx.x;
    const int j0   = bid * 4;
    const int w    = tid >> 5;
    const int lane = tid & 31;
    const bool L0  = (w < 4);
    const int jl   = L0 ? w : (w - 4);
    const int jg   = j0 + jl;

    // ---- resident weight slices: local row (jl*4 + gate) <- global row gate*HD + jg
    for (int idx = tid; idx < 16 * HD; idx += NT) {
        int r = idx >> 9, k = idx & (HD - 1);
        int row = (r & 3) * HD + j0 + (r >> 2);
        sU0[idx] = u0W[row * HD + k];
        sU1[idx] = u1W[row * HD + k];
        sW1[idx] = w1W[row * HD + k];
    }
    for (int idx = tid; idx < 16 * DI; idx += NT) {
        int r = idx >> 8, k = idx & (DI - 1);
        int row = (r & 3) * HD + j0 + (r >> 2);
        sW0[idx] = w0W[row * DI + k];
    }
    // per-warp gate biases in registers
    float bs0, bs1, bs2, bs3;
    {
        const float* ubp = L0 ? u0b : u1b;
        const float* wbp = L0 ? w0b : w1b;
        bs0 = ubp[0 * HD + jg] + wbp[0 * HD + jg];
        bs1 = ubp[1 * HD + jg] + wbp[1 * HD + jg];
        bs2 = ubp[2 * HD + jg] + wbp[2 * HD + jg];
        bs3 = ubp[3 * HD + jg] + wbp[3 * HD + jg];
    }
    float creg = 0.0f;   // cell state for (column jg, batch=lane) on lanes 0-7
    __syncthreads();

    for (int p = 0; p <= TT; p++) {
        unsigned long long acc[32];
#pragma unroll
        for (int j = 0; j < 32; j++) acc[j] = 0ull;

        // ---- phase 1: stage x(p) + W0*x dot (warps 0-3) overlapped with flag poll (warp 7)
        if (L0) {
            if (p < TT) {
                const float4* x4 = (const float4*)x;
                float4* sX4 = (float4*)sX;
                int i = w * 32 + lane;
#pragma unroll
                for (int rep = 0; rep < 4; rep++, i += 128) {
                    int b = i >> 6, d = i & 63;
                    sX4[i] = x4[(b * TT + p) * 64 + d];
                }
            }
            asm volatile("bar.sync 1, 128;" ::: "memory");
            if (p < TT) dot2<DI>(acc, sW0, sX, w * 4, lane);
        } else if (w == 7) {
            poll_flags(lane, (unsigned)p);
        }
        __syncthreads();

        // ---- phase 2: stage recurrent broadcasts from L2
        {
            const float4* a4 = (const float4*)(g_hA + (p & 1) * (BB * HD));
            const float4* b4 = (const float4*)(g_hB + ((p + 1) & 1) * (BB * HD));
            float4* sA4 = (float4*)sA;
            float4* sB4 = (float4*)sB;
            int i = tid;
#pragma unroll
            for (int rep = 0; rep < 4; rep++, i += NT) {
                sA4[i] = __ldcg(a4 + i);
                sB4[i] = __ldcg(b4 + i);
            }
        }
        __syncthreads();

        // ---- phase 3: recurrent dots
        const bool active = L0 ? (p < TT) : (p > 0);
        if (L0) {
            if (active) dot2<HD>(acc, sU0, sA, w * 4, lane);
        } else if (active) {
            dot2<HD>(acc, sU1, sB, jl * 4, lane);
            dot2<HD>(acc, sW1, sA, jl * 4, lane);
        }

        if (active) {
            // horizontal add of f32x2 halves
            float av[32];
#pragma unroll
            for (int j = 0; j < 32; j++) {
                unsigned lo, hi;
                asm("mov.b64 {%0,%1}, %2;" : "=r"(lo), "=r"(hi) : "l"(acc[j]));
                av[j] = __uint_as_float(lo) + __uint_as_float(hi);
            }
            // reduce-scatter: lane l ends owning (gate=l>>3, batch=l&7)
#pragma unroll
            for (int m = 16; m > 0; m >>= 1) {
                const bool hi = (lane & m) != 0;
#pragma unroll
                for (int j = 0; j < m; j++) {
                    float sendv = hi ? av[j] : av[j + m];
                    float other = __shfl_xor_sync(0xffffffffu, sendv, m);
                    av[j] = (hi ? av[j + m] : av[j]) + other;
                }
            }
            // gather the 4 gates of batch (lane&7)
            const int bsel = lane & 7;
            float vi = __shfl_sync(0xffffffffu, av[0], bsel);
            float vf = __shfl_sync(0xffffffffu, av[0], bsel + 8);
            float vg = __shfl_sync(0xffffffffu, av[0], bsel + 16);
            float vo = __shfl_sync(0xffffffffu, av[0], bsel + 24);

            if (lane < 8) {   // lane = batch
                float iv = sigm(vi + bs0);
                float fv = sigm(vf + bs1);
                float gv = tanh_fast(vg + bs2);
                float ov = sigm(vo + bs3);
                float c = fv * creg + iv * gv;
                creg = c;
                float h = ov * fmaxf(c, 0.0f);   // custom relu nonlinearity
                if (L0) {
                    __stcg(g_hA + ((p + 1) & 1) * (BB * HD) + lane * HD + jg, h);
                    if (p == TT - 1) { hh[lane * HD + jg] = h; cc[lane * HD + jg] = c; }
                } else {
                    const int t1 = p - 1;
                    __stcg(g_hB + (p & 1) * (BB * HD) + lane * HD + jg, h);
                    h2seq[(lane * TT + t1) * HD + jg] = h;
                    if (t1 == TT - 1) {
                        hh[BB * HD + lane * HD + jg] = h;
                        cc[BB * HD + lane * HD + jg] = c;
                    }
                }
            }
        }

        // ---- phase 4: publish completion of period p
        __syncthreads();
        if (tid == 0) {
            asm volatile("fence.acq_rel.gpu;" ::: "memory");
            unsigned v = (unsigned)(p + 1);
            asm volatile("st.relaxed.gpu.global.b32 [%0], %1;"
                         :: "l"(g_flags + bid), "r"(v) : "memory");
        }
    }
}

// ---------------- host launch ----------------
extern "C" void kernel_launch(void* const* d_in, const int* in_sizes, int n_in,
                              void* d_out, int out_size) {
    (void)in_sizes; (void)n_in; (void)out_size;
    const float* x   = (const float*)d_in[0];
    const float* w0w = (const float*)d_in[1];
    const float* w0b = (const float*)d_in[2];
    const float* u0w = (const float*)d_in[3];
    const float* u0b = (const float*)d_in[4];
    const float* w1w = (const float*)d_in[5];
    const float* w1b = (const float*)d_in[6];
    const float* u1w = (const float*)d_in[7];
    const float* u1b = (const float*)d_in[8];
    float* out = (float*)d_out;

    const size_t H2 = (size_t)BB * TT * HD;
    float* hh = out + H2;                     // [2, B, H]
    float* cc = hh + 2 * BB * HD;             // [2, B, H]

    const size_t smem = (size_t)(16 * HD * 3 + 16 * DI + 2 * BB * HD + BB * DI)
                        * sizeof(float);      // ~155.6 KB
    cudaFuncSetAttribute(lstm_fused_kernel, cudaFuncAttributeMaxDynamicSharedMemorySize,
                         (int)smem);

    init_kernel<<<16, 256>>>();
    lstm_fused_kernel<<<NB, NT, smem>>>(x, u0w, w0w, u0b, w0b,
                                        u1w, w1w, u1b, w1b,
                                        out, hh, cc);
}

// round 5
// speedup vs baseline: 1.5260x; 1.5260x over previous
#include <cuda_runtime.h>

#define NB 128   // persistent CTAs (1/SM, co-resident -> spin barrier safe)
#define NT 256   // 8 warps
#define TT 2048
#define BB 8
#define HD 512
#define DI 256

// ---------------- device scratch (no cudaMalloc allowed) ----------------
__device__ float g_hA[2 * BB * HD];      // double-buffered h1 broadcast
__device__ float g_hB[2 * BB * HD];      // double-buffered h2 broadcast
__device__ unsigned g_flags[NB];         // periods completed per CTA (4 L2 lines)

__global__ void init_kernel() {
    int i = blockIdx.x * blockDim.x + threadIdx.x;
    int stride = gridDim.x * blockDim.x;
    if (i < NB) g_flags[i] = 0u;
    for (int k = i; k < 2 * BB * HD; k += stride) { g_hA[k] = 0.0f; g_hB[k] = 0.0f; }
}

__device__ __forceinline__ float sigm(float x) {
    return __fdividef(1.0f, 1.0f + __expf(-x));
}
__device__ __forceinline__ float tanh_fast(float x) {
    return 2.0f * sigm(2.0f * x) - 1.0f;   // saturation-safe
}

// Packed dual-FMA on the sm_103a f32x2 pipe.
__device__ __forceinline__ void ffma2(unsigned long long& d, unsigned long long a,
                                      unsigned long long b) {
    asm("fma.rn.f32x2 %0, %1, %2, %0;" : "+l"(d) : "l"(a), "l"(b));
}

// Wait until every CTA has completed >= target periods. Acquire loads only
// (no atomics, no gpu-scope fence -> no CCTL.IVALL L1 flush).
__device__ __forceinline__ void poll_flags(int lane, unsigned target) {
    const unsigned* f = g_flags + lane;
    bool ok;
    do {
        unsigned a, b, c, d;
        asm volatile("ld.acquire.gpu.global.b32 %0, [%1];" : "=r"(a) : "l"(f)      : "memory");
        asm volatile("ld.acquire.gpu.global.b32 %0, [%1];" : "=r"(b) : "l"(f + 32) : "memory");
        asm volatile("ld.acquire.gpu.global.b32 %0, [%1];" : "=r"(c) : "l"(f + 64) : "memory");
        asm volatile("ld.acquire.gpu.global.b32 %0, [%1];" : "=r"(d) : "l"(f + 96) : "memory");
        ok = (a >= target) && (b >= target) && (c >= target) && (d >= target);
    } while (!__all_sync(0xffffffffu, ok));
}

// Register-weight dot: acc[g*8+b] += wgt[it][g] (lane's k-slice) * src[b].
// Only 8 LDS.128 per iter (src); weights come from registers.
template <int NIT, int STR>
__device__ __forceinline__ void dotr(unsigned long long* acc,
                                     const ulonglong2 (*wgt)[4],
                                     const float* __restrict__ src, int lane) {
#pragma unroll
    for (int it = 0; it < NIT; it++) {
        const float* s = src + it * 128 + lane * 4;
#pragma unroll
        for (int b = 0; b < 8; b++) {
            ulonglong2 v = *(const ulonglong2*)(s + b * STR);
#pragma unroll
            for (int g = 0; g < 4; g++) {
                ffma2(acc[g * 8 + b], wgt[it][g].x, v.x);
                ffma2(acc[g * 8 + b], wgt[it][g].y, v.y);
            }
        }
    }
}

// Horizontal f32x2 add + 31-shuffle reduce-scatter.
// Returns: lane l owns the total for (gate = l>>3, batch = l&7).
__device__ __forceinline__ float hreduce(const unsigned long long* acc, int lane) {
    float av[32];
#pragma unroll
    for (int j = 0; j < 32; j++) {
        unsigned lo, hi;
        asm("mov.b64 {%0,%1}, %2;" : "=r"(lo), "=r"(hi) : "l"(acc[j]));
        av[j] = __uint_as_float(lo) + __uint_as_float(hi);
    }
#pragma unroll
    for (int m = 16; m > 0; m >>= 1) {
        const bool hi = (lane & m) != 0;
#pragma unroll
        for (int j = 0; j < m; j++) {
            float sendv = hi ? av[j] : av[j + m];
            float other = __shfl_xor_sync(0xffffffffu, sendv, m);
            av[j] = (hi ? av[j + m] : av[j]) + other;
        }
    }
    return av[0];
}

// Fused 2-layer wavefront: period p = layer0 step p + layer1 step p-1.
// Warp = (layer, column): warps 0-3 own layer-0 columns j0..j0+3 (4 gates each),
// warps 4-7 the same columns of layer 1. All weights live in registers.
__global__ void __launch_bounds__(NT, 1) lstm_fused_kernel(
    const float* __restrict__ x,
    const float* __restrict__ u0W, const float* __restrict__ w0W,
    const float* __restrict__ u0b, const float* __restrict__ w0b,
    const float* __restrict__ u1W, const float* __restrict__ w1W,
    const float* __restrict__ u1b, const float* __restrict__ w1b,
    float* __restrict__ h2seq, float* __restrict__ hh, float* __restrict__ cc)
{
    extern __shared__ float sm[];
    float* sA = sm;                  // 8*512  h1(p-1) stage
    float* sB = sA + BB * HD;        // 8*512  h2(p-2) stage
    float* sX = sB + BB * HD;        // 2 x 8*256  x double buffer

    const int tid  = threadIdx.x;
    const int bid  = blockIdx.x;
    const int w    = tid >> 5;
    const int lane = tid & 31;
    const bool L0  = (w < 4);
    const int jl   = L0 ? w : (w - 4);
    const int jg   = bid * 4 + jl;

    // ---- weights into registers (constant for all 2048 steps) ----
    ulonglong2 wA[4][4];   // recurrent U (K=512): [k-iter][gate], lane k-slice
    ulonglong2 wB[4][4];   // input W: L0 uses [0..1] (K=256), L1 [0..3] (K=512)
    {
        const float* Up = L0 ? u0W : u1W;
#pragma unroll
        for (int it = 0; it < 4; it++)
#pragma unroll
            for (int g = 0; g < 4; g++)
                wA[it][g] = *(const ulonglong2*)(Up + (size_t)(g * HD + jg) * HD
                                                 + it * 128 + lane * 4);
        if (L0) {
#pragma unroll
            for (int it = 0; it < 2; it++)
#pragma unroll
                for (int g = 0; g < 4; g++)
                    wB[it][g] = *(const ulonglong2*)(w0W + (size_t)(g * HD + jg) * DI
                                                     + it * 128 + lane * 4);
        } else {
#pragma unroll
            for (int it = 0; it < 4; it++)
#pragma unroll
                for (int g = 0; g < 4; g++)
                    wB[it][g] = *(const ulonglong2*)(w1W + (size_t)(g * HD + jg) * HD
                                                     + it * 128 + lane * 4);
        }
    }
    float bs0, bs1, bs2, bs3;
    {
        const float* ubp = L0 ? u0b : u1b;
        const float* wbp = L0 ? w0b : w1b;
        bs0 = ubp[0 * HD + jg] + wbp[0 * HD + jg];
        bs1 = ubp[1 * HD + jg] + wbp[1 * HD + jg];
        bs2 = ubp[2 * HD + jg] + wbp[2 * HD + jg];
        bs3 = ubp[3 * HD + jg] + wbp[3 * HD + jg];
    }
    float creg = 0.0f;   // cell state (column jg, batch=lane) on lanes 0-7

    // ---- stage x(0) into sX buffer 0 ----
    {
        const float4* x4 = (const float4*)x;
        float4* sX4 = (float4*)sX;
#pragma unroll
        for (int r = 0; r < 2; r++) {
            int i = tid + r * NT;
            int b = i >> 6, d = i & 63;
            sX4[i] = x4[((size_t)b * TT + 0) * 64 + d];
        }
    }
    __syncthreads();

    for (int p = 0; p <= TT; p++) {
        // L2 prefetch of x(p+1) (64 x 128B lines)
        if (p + 1 < TT && tid < 64) {
            const float* pf = x + ((size_t)(tid >> 3) * TT + (p + 1)) * DI + (tid & 7) * 32;
            asm volatile("prefetch.global.L2 [%0];" :: "l"(pf));
        }

        // ---- phase 1 (no barrier needed): L0 warps do W0*x and pre-reduce it
        //      to one scalar per lane; then warp 3 polls the period-p barrier.
        float r0 = 0.0f;
        if (L0 && p < TT) {
            unsigned long long accx[32];
#pragma unroll
            for (int j = 0; j < 32; j++) accx[j] = 0ull;
            dotr<2, DI>(accx, wB, sX + (p & 1) * (BB * DI), lane);
            r0 = hreduce(accx, lane);
        }
        if (w == 3) poll_flags(lane, (unsigned)p);
        __syncthreads();

        // ---- phase 2: stage recurrent broadcasts from L2 (MLP=8) ----
        {
            const float4* a4 = (const float4*)(g_hA + (p & 1) * (BB * HD));
            const float4* b4 = (const float4*)(g_hB + ((p + 1) & 1) * (BB * HD));
            float4 va[4], vb[4];
#pragma unroll
            for (int r = 0; r < 4; r++) {
                va[r] = __ldcg(a4 + tid + r * NT);
                vb[r] = __ldcg(b4 + tid + r * NT);
            }
            float4* sA4 = (float4*)sA;
            float4* sB4 = (float4*)sB;
#pragma unroll
            for (int r = 0; r < 4; r++) {
                sA4[tid + r * NT] = va[r];
                sB4[tid + r * NT] = vb[r];
            }
        }
        __syncthreads();

        // ---- phase 3: recurrent dots from register weights ----
        const bool active = L0 ? (p < TT) : (p > 0);
        unsigned long long acc[32];
#pragma unroll
        for (int j = 0; j < 32; j++) acc[j] = 0ull;
        if (active) {
            if (L0) {
                dotr<4, HD>(acc, wA, sA, lane);
            } else {
                dotr<4, HD>(acc, wA, sB, lane);
                dotr<4, HD>(acc, wB, sA, lane);
            }
        }

        // issue x(p+1) loads (hit L2 via prefetch); STS after the reduce
        float4 xv0, xv1;
        const bool xp = (p + 1 < TT);
        if (xp) {
            const float4* x4 = (const float4*)x;
            int i0 = tid, i1 = tid + NT;
            xv0 = x4[((size_t)(i0 >> 6) * TT + (p + 1)) * 64 + (i0 & 63)];
            xv1 = x4[((size_t)(i1 >> 6) * TT + (p + 1)) * 64 + (i1 & 63)];
        }

        if (active) {
            float v = hreduce(acc, lane) + r0;   // r0 = 0 on L1 warps
            // gather the 4 gates of batch (lane&7)
            const int bsel = lane & 7;
            float vi = __shfl_sync(0xffffffffu, v, bsel);
            float vf = __shfl_sync(0xffffffffu, v, bsel + 8);
            float vg = __shfl_sync(0xffffffffu, v, bsel + 16);
            float vo = __shfl_sync(0xffffffffu, v, bsel + 24);

            if (lane < 8) {   // lane = batch
                float iv = sigm(vi + bs0);
                float fv = sigm(vf + bs1);
                float gv = tanh_fast(vg + bs2);
                float ov = sigm(vo + bs3);
                float c = fv * creg + iv * gv;
                creg = c;
                float h = ov * fmaxf(c, 0.0f);   // custom relu nonlinearity
                if (L0) {
                    __stcg(g_hA + ((p + 1) & 1) * (BB * HD) + lane * HD + jg, h);
                    if (p == TT - 1) { hh[lane * HD + jg] = h; cc[lane * HD + jg] = c; }
                } else {
                    const int t1 = p - 1;
                    __stcg(g_hB + (p & 1) * (BB * HD) + lane * HD + jg, h);
                    h2seq[((size_t)lane * TT + t1) * HD + jg] = h;
                    if (t1 == TT - 1) {
                        hh[BB * HD + lane * HD + jg] = h;
                        cc[BB * HD + lane * HD + jg] = c;
                    }
                }
            }
        }

        // stage x(p+1) into the other buffer (readers of this parity finished
        // in period p-1, before this period's opening __syncthreads)
        if (xp) {
            float4* sX4 = (float4*)(sX + ((p + 1) & 1) * (BB * DI));
            sX4[tid] = xv0;
            sX4[tid + NT] = xv1;
        }

        // ---- publish completion of period p (release store; no gpu fence,
        //      no CCTL.IVALL) ----
        __syncthreads();
        if (tid == 0) {
            unsigned v = (unsigned)(p + 1);
            asm volatile("st.release.gpu.global.b32 [%0], %1;"
                         :: "l"(g_flags + bid), "r"(v) : "memory");
        }
    }
}

// ---------------- host launch ----------------
extern "C" void kernel_launch(void* const* d_in, const int* in_sizes, int n_in,
                              void* d_out, int out_size) {
    (void)in_sizes; (void)n_in; (void)out_size;
    const float* x   = (const float*)d_in[0];
    const float* w0w = (const float*)d_in[1];
    const float* w0b = (const float*)d_in[2];
    const float* u0w = (const float*)d_in[3];
    const float* u0b = (const float*)d_in[4];
    const float* w1w = (const float*)d_in[5];
    const float* w1b = (const float*)d_in[6];
    const float* u1w = (const float*)d_in[7];
    const float* u1b = (const float*)d_in[8];
    float* out = (float*)d_out;

    const size_t H2 = (size_t)BB * TT * HD;
    float* hh = out + H2;                     // [2, B, H]
    float* cc = hh + 2 * BB * HD;             // [2, B, H]

    const size_t smem = (size_t)(2 * BB * HD + 2 * BB * DI) * sizeof(float);  // 48 KB
    cudaFuncSetAttribute(lstm_fused_kernel, cudaFuncAttributeMaxDynamicSharedMemorySize,
                         (int)smem);

    init_kernel<<<16, 256>>>();
    lstm_fused_kernel<<<NB, NT, smem>>>(x, u0w, w0w, u0b, w0b,
                                        u1w, w1w, u1b, w1b,
                                        out, hh, cc);
}